// round 10
// baseline (speedup 1.0000x reference)
#include <cuda_runtime.h>
#include <cstdint>

#define S_LEN 2048
#define B_SZ  256
#define H_SZ  256
#define NI    128
#define NO    128

typedef unsigned long long ull;

// Scratch (allocation-free)
__device__ float g_Zx[(size_t)S_LEN * B_SZ * H_SZ];   // (t, b, h)
__device__ float g_H [(size_t)S_LEN * B_SZ * H_SZ];   // (t, b, k)
__device__ float g_sum[S_LEN][H_SZ];                  // per-step BN sum (RED)
__device__ float g_sq [S_LEN][H_SZ];                  // per-step BN sumsq (RED)
__device__ unsigned g_cnt[32];                        // padded step counter

__device__ __forceinline__ float gelu_f(float x) {
    return 0.5f * x * (1.0f + erff(x * 0.70710678118654752440f));
}

// ---- packed f32x2 helpers (sm_103a) ----
__device__ __forceinline__ void fma2(ull& d, ull a, ull b) {
    asm("fma.rn.f32x2 %0, %1, %2, %3;" : "=l"(d) : "l"(a), "l"(b), "l"(d));
}
__device__ __forceinline__ ull pack2(float x, float y) {
    ull r; asm("mov.b64 %0, {%1, %2};" : "=l"(r) : "f"(x), "f"(y)); return r;
}
__device__ __forceinline__ float2 unpack2(ull v) {
    float2 f; asm("mov.b64 {%0, %1}, %2;" : "=f"(f.x), "=f"(f.y) : "l"(v)); return f;
}

// ---- cluster / sync helpers ----
__device__ __forceinline__ unsigned ctarank() {
    unsigned r; asm("mov.u32 %0, %%cluster_ctarank;" : "=r"(r)); return r;
}
__device__ __forceinline__ unsigned smem_u32(const void* p) {
    return (unsigned)__cvta_generic_to_shared(p);
}
__device__ __forceinline__ unsigned mapa_peer(unsigned laddr, unsigned rank) {
    unsigned r;
    asm("mapa.shared::cluster.u32 %0, %1, %2;" : "=r"(r) : "r"(laddr), "r"(rank));
    return r;
}
__device__ __forceinline__ void st_cluster_f2(unsigned addr, float x, float y) {
    asm volatile("st.shared::cluster.v2.f32 [%0], {%1, %2};"
                 :: "r"(addr), "f"(x), "f"(y) : "memory");
}
__device__ __forceinline__ void cluster_sync_() {
    asm volatile("barrier.cluster.arrive.aligned;" ::: "memory");
    asm volatile("barrier.cluster.wait.aligned;" ::: "memory");
}
__device__ __forceinline__ void red_addf(float* p, float v) {
    asm volatile("red.global.add.f32 [%0], %1;" :: "l"(p), "f"(v) : "memory");
}
__device__ __forceinline__ void mbar_init(unsigned addr, unsigned cnt) {
    asm volatile("mbarrier.init.shared.b64 [%0], %1;" :: "r"(addr), "r"(cnt) : "memory");
}
__device__ __forceinline__ void mbar_arrive_peer(unsigned addr, unsigned rank) {
    asm volatile(
        "{\n\t.reg .b32 ra;\n\t"
        "mapa.shared::cluster.u32 ra, %0, %1;\n\t"
        "mbarrier.arrive.release.cluster.shared::cluster.b64 _, [ra];\n\t}"
        :: "r"(addr), "r"(rank) : "memory");
}
__device__ __forceinline__ void mbar_wait_parity(unsigned addr, unsigned parity) {
    unsigned done;
    asm volatile(
        "{\n\t.reg .pred p;\n\t"
        "mbarrier.try_wait.parity.acquire.cluster.shared::cta.b64 p, [%1], %2;\n\t"
        "selp.b32 %0, 1, 0, p;\n\t}"
        : "=r"(done) : "r"(addr), "r"(parity) : "memory");
    while (!done) {
        asm volatile(
            "{\n\t.reg .pred p;\n\t"
            "mbarrier.try_wait.parity.acquire.cluster.shared::cta.b64 p, [%1], %2, 0x989680;\n\t"
            "selp.b32 %0, 1, 0, p;\n\t}"
            : "=r"(done) : "r"(addr), "r"(parity) : "memory");
    }
}

__global__ void init_kernel() {
    const size_t n = (size_t)S_LEN * H_SZ;
    const size_t stride = (size_t)gridDim.x * blockDim.x;
    for (size_t i = (size_t)blockIdx.x * blockDim.x + threadIdx.x; i < n; i += stride) {
        ((float*)g_sum)[i] = 0.f;
        ((float*)g_sq)[i]  = 0.f;
    }
    if (blockIdx.x == 0 && threadIdx.x < 32) g_cnt[threadIdx.x] = 0u;
}

// ---------------------------------------------------------------------------
// Kernel A: Zx[t,b,n] = sum_i X[b,t,i] * W_ih[n,i] + b_ih[n]
// ---------------------------------------------------------------------------
__global__ void __launch_bounds__(256) proj_in_kernel(
    const float* __restrict__ X, const float* __restrict__ W_ih,
    const float* __restrict__ b_ih)
{
    __shared__ float As[16][132];
    __shared__ float Bs[16][68];
    const int tid = threadIdx.x;
    const int r0  = blockIdx.x * 128;
    const int n0  = blockIdx.y * 64;
    const int t   = r0 >> 8;
    const int b0  = r0 & 255;
    const int tx  = tid & 15, ty = tid >> 4;

    float acc[8][4];
    #pragma unroll
    for (int i = 0; i < 8; ++i)
        #pragma unroll
        for (int j = 0; j < 4; ++j) acc[i][j] = 0.f;

    const int kq = (tid & 3) * 4;
    const int am = tid >> 2;

    for (int k0 = 0; k0 < NI; k0 += 16) {
        #pragma unroll
        for (int h = 0; h < 2; ++h) {
            const int m = am + h * 64;
            const float4 v = *(const float4*)(X + (size_t)(b0 + m) * (S_LEN * NI)
                                              + (size_t)t * NI + k0 + kq);
            As[kq + 0][m] = v.x; As[kq + 1][m] = v.y;
            As[kq + 2][m] = v.z; As[kq + 3][m] = v.w;
        }
        {
            const float4 v = *(const float4*)(W_ih + (size_t)(n0 + am) * 384 + k0 + kq);
            Bs[kq + 0][am] = v.x; Bs[kq + 1][am] = v.y;
            Bs[kq + 2][am] = v.z; Bs[kq + 3][am] = v.w;
        }
        __syncthreads();
        #pragma unroll
        for (int kk = 0; kk < 16; ++kk) {
            const float4 a0 = *(const float4*)&As[kk][ty * 8];
            const float4 a1 = *(const float4*)&As[kk][ty * 8 + 4];
            const float4 bv = *(const float4*)&Bs[kk][tx * 4];
            const float a[8] = {a0.x, a0.y, a0.z, a0.w, a1.x, a1.y, a1.z, a1.w};
            const float bb[4] = {bv.x, bv.y, bv.z, bv.w};
            #pragma unroll
            for (int i = 0; i < 8; ++i)
                #pragma unroll
                for (int j = 0; j < 4; ++j) acc[i][j] = fmaf(a[i], bb[j], acc[i][j]);
        }
        __syncthreads();
    }
    const float4 bv = *(const float4*)(b_ih + n0 + tx * 4);
    #pragma unroll
    for (int i = 0; i < 8; ++i) {
        float4 o;
        o.x = acc[i][0] + bv.x; o.y = acc[i][1] + bv.y;
        o.z = acc[i][2] + bv.z; o.w = acc[i][3] + bv.w;
        *(float4*)(g_Zx + (size_t)(r0 + ty * 8 + i) * 256 + n0 + tx * 4) = o;
    }
}

// ---------------------------------------------------------------------------
// Kernel B: k-split clustered recurrence; rank-split tail; mbarrier handshake.
// 64 clusters x 2 CTAs; cluster owns 4 batch rows; CTA rank owns k-half of
// W_h in registers. Per step:
//   matvec (own k-half, all 256 cols) -> redb -> S1 ->
//   warps 0-3 combine + push peer-col partials (2KB DSMEM) -> warp-elect
//   mbarrier arrive (count 4) -> parity wait ->
//   finalize OWN 128 cols (thread = col x 2 rows) -> s,q partials -> S2 ->
//   tid<128 combine + RED (64-way) -> S2b -> tid0 fence+atomic+poll -> S3 ->
//   stats -> gelu (2 erf) -> h2 + g_H (own cols) -> S4.
// ---------------------------------------------------------------------------
__global__ void __launch_bounds__(256, 1) __cluster_dims__(2, 1, 1)
rec_kernel(const float* __restrict__ W_ih, const float* __restrict__ gamma,
           const float* __restrict__ beta)
{
    __shared__ float  h2[128][8];        // own k-half h, 4 rows dup pairs (4 KB)
    __shared__ float2 redb[2][4][128];   // own partials [kq][row][cp] (4 KB)
    __shared__ float2 zbuf[2][4][64];    // peer partials for OWN cols (2 KB)
    __shared__ float2 sqp[2][128];       // {s,q} row-pair partials (1 KB)
    __shared__ ull    mbar;

    const int tid  = threadIdx.x;
    const unsigned rank = ctarank();
    const int b0   = (blockIdx.x >> 1) * 4;
    const int kq   = tid >> 7;           // matvec: 64-k quarter of own k-half
    const int cp   = tid & 127;          // matvec: global col pair
    const int c2   = cp * 2;

    // W quarter in registers: wreg[i] = {W[gk][c2], W[gk][c2+1]},
    // gk = rank*128 + kq*64 + i
    ull wreg[64];
    {
        const int kbase = NI + (int)rank * 128 + kq * 64;
        const float* w0p = W_ih + (size_t)c2 * 384 + kbase;
        const float* w1p = W_ih + (size_t)(c2 + 1) * 384 + kbase;
        #pragma unroll
        for (int i = 0; i < 64; ++i) wreg[i] = pack2(w0p[i], w1p[i]);
    }
    // tail role: own column gc, row pair rh
    const int col_l = tid & 127;
    const int rh    = tid >> 7;          // 0: rows 0,1   1: rows 2,3
    const int gc    = (int)rank * 128 + col_l;
    const float gam = gamma[gc];
    const float bet = beta[gc];

    if (tid == 0) mbar_init(smem_u32(&mbar), 4);
    cluster_sync_();   // mbar visible cluster-wide before first remote arrive

    volatile unsigned* vcnt = (volatile unsigned*)&g_cnt[0];

    for (int t = 0; t < S_LEN; ++t) {
        // prefetch Zx for own (col, 2 rows)
        const float zx_a = __ldcg(g_Zx + ((size_t)t * 256 + b0 + 2 * rh) * 256 + gc);
        const float zx_b = __ldcg(g_Zx + ((size_t)t * 256 + b0 + 2 * rh + 1) * 256 + gc);

        ull a0 = 0ull, a1 = 0ull, a2 = 0ull, a3 = 0ull;
        if (t > 0) {
            const int kb = kq * 64;
            #pragma unroll
            for (int i = 0; i < 64; ++i) {
                const ulonglong2 p01 = *(const ulonglong2*)&h2[kb + i][0];
                const ulonglong2 p23 = *(const ulonglong2*)&h2[kb + i][4];
                fma2(a0, p01.x, wreg[i]);
                fma2(a1, p01.y, wreg[i]);
                fma2(a2, p23.x, wreg[i]);
                fma2(a3, p23.y, wreg[i]);
            }
        }
        redb[kq][0][cp] = unpack2(a0);
        redb[kq][1][cp] = unpack2(a1);
        redb[kq][2][cp] = unpack2(a2);
        redb[kq][3][cp] = unpack2(a3);
        __syncthreads();                               // S1

        const int par = t & 1;
        // warps 0-3: combine both k-quarters for PEER cols, push to peer zbuf
        if (tid < 128) {
            const int j   = tid & 63;                  // peer col-pair local idx
            const int rp  = (tid >> 6) & 1;            // row half
            const int pcp = ((int)(rank ^ 1u)) * 64 + j;
            #pragma unroll
            for (int rr = 0; rr < 2; ++rr) {
                const int r = 2 * rp + rr;
                const float2 o0 = redb[0][r][pcp];
                const float2 o1 = redb[1][r][pcp];
                st_cluster_f2(mapa_peer(smem_u32(&zbuf[par][r][j]), rank ^ 1u),
                              o0.x + o1.x, o0.y + o1.y);
            }
            __syncwarp();
            if ((tid & 31) == 0) mbar_arrive_peer(smem_u32(&mbar), rank ^ 1u);
        }
        mbar_wait_parity(smem_u32(&mbar), (unsigned)par);

        // finalize OWN cols: z for (gc, rows 2rh, 2rh+1)
        const int cpo  = gc >> 1;                      // own global col pair
        const int jown = col_l >> 1;                   // own zbuf idx
        float z_a, z_b;
        {
            const float2 ra0 = redb[0][2 * rh][cpo];
            const float2 rb0 = redb[1][2 * rh][cpo];
            const float2 zp0 = zbuf[par][2 * rh][jown];
            const float2 ra1 = redb[0][2 * rh + 1][cpo];
            const float2 rb1 = redb[1][2 * rh + 1][cpo];
            const float2 zp1 = zbuf[par][2 * rh + 1][jown];
            if (gc & 1) {
                z_a = (ra0.y + rb0.y) + zp0.y + zx_a;
                z_b = (ra1.y + rb1.y) + zp1.y + zx_b;
            } else {
                z_a = (ra0.x + rb0.x) + zp0.x + zx_a;
                z_b = (ra1.x + rb1.x) + zp1.x + zx_b;
            }
        }
        sqp[rh][col_l] = make_float2(z_a + z_b, z_a * z_a + z_b * z_b);
        __syncthreads();                               // S2
        if (tid < 128) {
            const float2 p0 = sqp[0][tid];
            const float2 p1 = sqp[1][tid];
            red_addf(&g_sum[t][(int)rank * 128 + tid], p0.x + p1.x);
            red_addf(&g_sq [t][(int)rank * 128 + tid], p0.y + p1.y);
        }
        __syncthreads();                               // S2b
        if (tid == 0) {
            __threadfence();                           // order this CTA's REDs
            atomicAdd(&g_cnt[0], 1u);
            const unsigned tgt = 128u * (unsigned)(t + 1);
            while (*vcnt < tgt) { }
            __threadfence();
        }
        __syncthreads();                               // S3

        const float sm = __ldcg(&g_sum[t][gc]);
        const float sq = __ldcg(&g_sq[t][gc]);
        const float mu  = sm * (1.f / 256.f);
        const float var = fmaf(-mu, mu, sq * (1.f / 256.f));
        const float ks  = rsqrtf(var + 1e-5f) * gam;
        const float h_a = gelu_f(fmaf(z_a - mu, ks, bet));
        const float h_b = gelu_f(fmaf(z_b - mu, ks, bet));

        // h2 (own cols ARE own k-half): rows 2rh, 2rh+1 as dup pairs
        *(float4*)&h2[col_l][4 * rh] = make_float4(h_a, h_a, h_b, h_b);
        // g_H (t,b,k): own cols, 2 rows, coalesced 128-wide
        g_H[((size_t)t * 256 + b0 + 2 * rh) * 256 + gc]     = h_a;
        g_H[((size_t)t * 256 + b0 + 2 * rh + 1) * 256 + gc] = h_b;
        __syncthreads();                               // S4: h2 ready
    }
}

// ---------------------------------------------------------------------------
// Kernel C: out[b,t,n] = gelu( sum_k H[t,b,k] * W_ho[n,k] + b_ho[n] )
// ---------------------------------------------------------------------------
__global__ void __launch_bounds__(256) proj_out_kernel(
    const float* __restrict__ W_ho, const float* __restrict__ b_ho,
    float* __restrict__ out)
{
    __shared__ float As[16][132];
    __shared__ float Bs[16][68];
    const int tid = threadIdx.x;
    const int r0  = blockIdx.x * 128;
    const int n0  = blockIdx.y * 64;
    const int t   = r0 >> 8;
    const int b0  = r0 & 255;
    const int tx  = tid & 15, ty = tid >> 4;

    float acc[8][4];
    #pragma unroll
    for (int i = 0; i < 8; ++i)
        #pragma unroll
        for (int j = 0; j < 4; ++j) acc[i][j] = 0.f;

    const int kq = (tid & 3) * 4;
    const int am = tid >> 2;

    for (int k0 = 0; k0 < H_SZ; k0 += 16) {
        #pragma unroll
        for (int h = 0; h < 2; ++h) {
            const int m = am + h * 64;
            const float4 v = *(const float4*)(g_H + (size_t)(r0 + m) * 256 + k0 + kq);
            As[kq + 0][m] = v.x; As[kq + 1][m] = v.y;
            As[kq + 2][m] = v.z; As[kq + 3][m] = v.w;
        }
        {
            const float4 v = *(const float4*)(W_ho + (size_t)(n0 + am) * H_SZ + k0 + kq);
            Bs[kq + 0][am] = v.x; Bs[kq + 1][am] = v.y;
            Bs[kq + 2][am] = v.z; Bs[kq + 3][am] = v.w;
        }
        __syncthreads();
        #pragma unroll
        for (int kk = 0; kk < 16; ++kk) {
            const float4 a0 = *(const float4*)&As[kk][ty * 8];
            const float4 a1 = *(const float4*)&As[kk][ty * 8 + 4];
            const float4 bv = *(const float4*)&Bs[kk][tx * 4];
            const float a[8] = {a0.x, a0.y, a0.z, a0.w, a1.x, a1.y, a1.z, a1.w};
            const float bb[4] = {bv.x, bv.y, bv.z, bv.w};
            #pragma unroll
            for (int i = 0; i < 8; ++i)
                #pragma unroll
                for (int j = 0; j < 4; ++j) acc[i][j] = fmaf(a[i], bb[j], acc[i][j]);
        }
        __syncthreads();
    }
    const float4 bv = *(const float4*)(b_ho + n0 + tx * 4);
    #pragma unroll
    for (int i = 0; i < 8; ++i) {
        float4 o;
        o.x = gelu_f(acc[i][0] + bv.x);
        o.y = gelu_f(acc[i][1] + bv.y);
        o.z = gelu_f(acc[i][2] + bv.z);
        o.w = gelu_f(acc[i][3] + bv.w);
        *(float4*)(out + (size_t)(b0 + ty * 8 + i) * (S_LEN * NO)
                   + (size_t)t * NO + n0 + tx * 4) = o;
    }
}

// ---------------------------------------------------------------------------
extern "C" void kernel_launch(void* const* d_in, const int* in_sizes, int n_in,
                              void* d_out, int out_size)
{
    const float* X     = (const float*)d_in[0];
    const float* W_ih  = (const float*)d_in[1];
    const float* b_ih  = (const float*)d_in[2];
    const float* W_ho  = (const float*)d_in[3];
    const float* b_ho  = (const float*)d_in[4];
    const float* gamma = (const float*)d_in[5];
    const float* beta  = (const float*)d_in[6];
    float* out = (float*)d_out;

    init_kernel<<<256, 256>>>();
    proj_in_kernel<<<dim3((S_LEN * B_SZ) / 128, H_SZ / 64), 256>>>(X, W_ih, b_ih);
    rec_kernel<<<128, 256>>>(W_ih, gamma, beta);
    proj_out_kernel<<<dim3((S_LEN * B_SZ) / 128, NO / 64), 256>>>(W_ho, b_ho, out);
}